// round 7
// baseline (speedup 1.0000x reference)
#include <cuda_runtime.h>
#include <cuda_bf16.h>
#include <mma.h>

using namespace nvcuda;

#define B_ 256
#define L_ 1026
#define D_ 1280
#define E_ 300
#define H_ 256
#define C_ 1580   // D_+E_

// SMEM layouts for the wmma GEMM
#define A_LD 20   // As[64][20]  (m-major, padded)
#define B_LD 68   // Bs[16][68]  (k-major, padded)

// ---- scratch (device globals; no allocation allowed) ----
__device__ float g_pooled[B_ * D_];
__device__ float g_x1[B_ * D_];      // PRE-relu x1 (consumers apply relu)
__device__ float g_q[B_ * E_];
__device__ float g_attn[B_ * B_];
__device__ float g_f1[B_ * E_];
__device__ float g_f2[B_ * D_];
__device__ float g_comb[B_ * C_];
__device__ float g_h[B_ * H_];

// ------------------------------------------------------------------
// init accumulators: x1 <- b_prot, q <- b_attn, f1/f2/attn/h <- 0
// ------------------------------------------------------------------
__global__ void init_all_kernel(const float* __restrict__ b_prot,
                                const float* __restrict__ b_attn) {
    int i = blockIdx.x * blockDim.x + threadIdx.x;
    if (i < B_ * D_) {
        g_f2[i] = 0.f;
        g_x1[i] = b_prot[i % D_];
    }
    if (i < B_ * E_) {
        g_f1[i] = 0.f;
        g_q[i] = b_attn[i % E_];
    }
    if (i < B_ * B_) g_attn[i] = 0.f;
    if (i < B_ * H_) g_h[i] = 0.f;
}

// ------------------------------------------------------------------
// ragged masked mean pooling, DIRECT WRITE (no atomics, no pre-zero):
// grid (B, D/128), block 128; each thread owns one column, walks
// the full [1, len-1) span, writes sum * 1/(len-2).
// ------------------------------------------------------------------
__global__ void pool_kernel(const float* __restrict__ tok,
                            const int* __restrict__ lens) {
    int b = blockIdx.x;
    int d = blockIdx.y * 128 + threadIdx.x;
    int len = lens[b];
    int lend = len - 1;
    const float* base = tok + (size_t)b * L_ * D_ + d;
    float acc = 0.f;
    int l = 1;
    for (; l + 4 <= lend; l += 4) {
        float v0 = base[(size_t)l * D_];
        float v1 = base[(size_t)(l + 1) * D_];
        float v2 = base[(size_t)(l + 2) * D_];
        float v3 = base[(size_t)(l + 3) * D_];
        acc += (v0 + v1) + (v2 + v3);
    }
    for (; l < lend; l++) acc += base[(size_t)l * D_];
    float inv = 1.f / fmaxf((float)(len - 2), 1.f);
    g_pooled[b * D_ + d] = acc * inv;
}

// ------------------------------------------------------------------
// split-K tf32 wmma GEMM body (shared by single + dual kernels).
//   C[M,N] += sum_{k in split} A_eff(m,k)*B_eff(k,n)
//   A_eff(m,k) = TA ? A[k*lda+m] : A[m*lda+k]   (relu'd if RELUA)
//   B_eff(k,n) = TB ? B[n*ldb+k] : B[k*ldb+n]   (relu'd if RELUB)
// BM=BN=64, BK=16, 256 threads (8 warps, 2x4). C pre-initialized.
// ------------------------------------------------------------------
template <int TA, int TB, int RELUA, int RELUB>
__device__ __forceinline__ void gemm_body(float* smem,
                                          const float* __restrict__ A,
                                          const float* __restrict__ B,
                                          float* __restrict__ C,
                                          int M, int N, int K, int lda, int ldb,
                                          int tiles_per_split, int zi) {
    float* As = smem;              // [64][A_LD]
    float* Bs = smem + 1280;       // [16][B_LD]

    int k_begin = zi * tiles_per_split * 16;
    if (k_begin >= K) return;
    int k_end = min(k_begin + tiles_per_split * 16, K);

    int t = threadIdx.x;
    int bm = blockIdx.y * 64;
    int bn = blockIdx.x * 64;
    int wid = t >> 5;
    int warp_m = wid & 1;
    int warp_n = wid >> 1;

    wmma::fragment<wmma::accumulator, 16, 16, 8, float> cf[2];
    wmma::fill_fragment(cf[0], 0.f);
    wmma::fill_fragment(cf[1], 0.f);

    for (int k0 = k_begin; k0 < k_end; k0 += 16) {
        // ---- stage A tile -> As[m][k] ----
        if (!TA) {
            int mm = t >> 2;
            int kk4 = (t & 3) * 4;
            float4 v = make_float4(0.f, 0.f, 0.f, 0.f);
            if (k0 + kk4 < K)
                v = *reinterpret_cast<const float4*>(
                        &A[(size_t)(bm + mm) * lda + k0 + kk4]);
            if (RELUA) {
                v.x = fmaxf(v.x, 0.f); v.y = fmaxf(v.y, 0.f);
                v.z = fmaxf(v.z, 0.f); v.w = fmaxf(v.w, 0.f);
            }
            *reinterpret_cast<float4*>(&As[mm * A_LD + kk4]) = v;
        } else {
            int kk = t >> 4;
            int mm4 = (t & 15) * 4;
            float4 v = make_float4(0.f, 0.f, 0.f, 0.f);
            if (k0 + kk < K)
                v = *reinterpret_cast<const float4*>(
                        &A[(size_t)(k0 + kk) * lda + bm + mm4]);
            if (RELUA) {
                v.x = fmaxf(v.x, 0.f); v.y = fmaxf(v.y, 0.f);
                v.z = fmaxf(v.z, 0.f); v.w = fmaxf(v.w, 0.f);
            }
            As[(mm4 + 0) * A_LD + kk] = v.x;
            As[(mm4 + 1) * A_LD + kk] = v.y;
            As[(mm4 + 2) * A_LD + kk] = v.z;
            As[(mm4 + 3) * A_LD + kk] = v.w;
        }
        // ---- stage B tile -> Bs[k][n] ----
        if (!TB) {
            int kk = t >> 4;
            int nn4 = (t & 15) * 4;
            float4 v = make_float4(0.f, 0.f, 0.f, 0.f);
            if (k0 + kk < K && bn + nn4 < N)
                v = *reinterpret_cast<const float4*>(
                        &B[(size_t)(k0 + kk) * ldb + bn + nn4]);
            if (RELUB) {
                v.x = fmaxf(v.x, 0.f); v.y = fmaxf(v.y, 0.f);
                v.z = fmaxf(v.z, 0.f); v.w = fmaxf(v.w, 0.f);
            }
            *reinterpret_cast<float4*>(&Bs[kk * B_LD + nn4]) = v;
        } else {
            int nn = t >> 2;
            int kk4 = (t & 3) * 4;
            float4 v = make_float4(0.f, 0.f, 0.f, 0.f);
            if (bn + nn < N && k0 + kk4 < K)
                v = *reinterpret_cast<const float4*>(
                        &B[(size_t)(bn + nn) * ldb + k0 + kk4]);
            if (RELUB) {
                v.x = fmaxf(v.x, 0.f); v.y = fmaxf(v.y, 0.f);
                v.z = fmaxf(v.z, 0.f); v.w = fmaxf(v.w, 0.f);
            }
            Bs[(kk4 + 0) * B_LD + nn] = v.x;
            Bs[(kk4 + 1) * B_LD + nn] = v.y;
            Bs[(kk4 + 2) * B_LD + nn] = v.z;
            Bs[(kk4 + 3) * B_LD + nn] = v.w;
        }
        __syncthreads();

#pragma unroll
        for (int kk = 0; kk < 16; kk += 8) {
            wmma::fragment<wmma::matrix_b, 16, 16, 8,
                           wmma::precision::tf32, wmma::row_major> bf;
            wmma::load_matrix_sync(bf, &Bs[kk * B_LD + warp_n * 16], B_LD);
#pragma unroll
            for (int i = 0; i < bf.num_elements; i++)
                bf.x[i] = wmma::__float_to_tf32(bf.x[i]);
#pragma unroll
            for (int ma = 0; ma < 2; ma++) {
                wmma::fragment<wmma::matrix_a, 16, 16, 8,
                               wmma::precision::tf32, wmma::row_major> af;
                wmma::load_matrix_sync(
                    af, &As[(warp_m * 32 + ma * 16) * A_LD + kk], A_LD);
#pragma unroll
                for (int i = 0; i < af.num_elements; i++)
                    af.x[i] = wmma::__float_to_tf32(af.x[i]);
                wmma::mma_sync(cf[ma], af, bf, cf[ma]);
            }
        }
        __syncthreads();
    }

    // ---- epilogue: stage fragments to SMEM, then atomicAdd to C ----
    float* epi = smem + wid * 512;
    wmma::store_matrix_sync(epi, cf[0], 16, wmma::mem_row_major);
    wmma::store_matrix_sync(epi + 256, cf[1], 16, wmma::mem_row_major);
    __syncwarp();

    int lane = t & 31;
    for (int idx = lane; idx < 512; idx += 32) {
        int ma = idx >> 8;
        int r = (idx & 255) >> 4;
        int c = idx & 15;
        int gm = bm + warp_m * 32 + ma * 16 + r;
        int gn = bn + warp_n * 16 + c;
        if (gn < N)
            atomicAdd(&C[(size_t)gm * N + gn], epi[ma * 256 + r * 16 + c]);
    }
}

template <int TA, int TB, int RELUA, int RELUB>
__global__ void gemm_kernel(const float* __restrict__ A,
                            const float* __restrict__ B,
                            float* __restrict__ C,
                            int M, int N, int K, int lda, int ldb,
                            int tiles_per_split) {
    __shared__ float smem[4096];
    gemm_body<TA, TB, RELUA, RELUB>(smem, A, B, C, M, N, K, lda, ldb,
                                    tiles_per_split, blockIdx.z);
}

// ------------------------------------------------------------------
// fused steps 6+7: blockIdx.z < z1 -> f1 = attn @ x2 ;
//                  else            -> f2 = attn^T @ relu(x1)
// grid (20, 4, z1+z2); f1 blocks with blockIdx.x >= 5 exit.
// ------------------------------------------------------------------
__global__ void gemm67_kernel(const float* __restrict__ attn,
                              const float* __restrict__ x2,
                              int z1, int tps1, int tps2) {
    __shared__ float smem[4096];
    if ((int)blockIdx.z < z1) {
        if (blockIdx.x >= (E_ + 63) / 64) return;
        gemm_body<0, 0, 0, 0>(smem, attn, x2, g_f1,
                              B_, E_, B_, B_, E_, tps1, blockIdx.z);
    } else {
        gemm_body<1, 0, 0, 1>(smem, attn, g_x1, g_f2,
                              B_, D_, B_, B_, D_, tps2, blockIdx.z - z1);
    }
}

// ------------------------------------------------------------------
// row softmax in-place: one block (256 threads) per row
// ------------------------------------------------------------------
__global__ void row_softmax_kernel(float* __restrict__ X, int N) {
    int r = blockIdx.x;
    float* x = X + (size_t)r * N;
    int t = threadIdx.x;
    __shared__ float red[8];

    float m = -1e30f;
    for (int i = t; i < N; i += 256) m = fmaxf(m, x[i]);
#pragma unroll
    for (int o = 16; o > 0; o >>= 1) m = fmaxf(m, __shfl_xor_sync(0xffffffffu, m, o));
    if ((t & 31) == 0) red[t >> 5] = m;
    __syncthreads();
    if (t < 8) {
        float v = red[t];
#pragma unroll
        for (int o = 4; o > 0; o >>= 1) v = fmaxf(v, __shfl_xor_sync(0xffu, v, o));
        if (t == 0) red[0] = v;
    }
    __syncthreads();
    m = red[0];
    __syncthreads();

    float s = 0.f;
    for (int i = t; i < N; i += 256) {
        float e = __expf(x[i] - m);
        x[i] = e;
        s += e;
    }
#pragma unroll
    for (int o = 16; o > 0; o >>= 1) s += __shfl_xor_sync(0xffffffffu, s, o);
    if ((t & 31) == 0) red[t >> 5] = s;
    __syncthreads();
    if (t < 8) {
        float v = red[t];
#pragma unroll
        for (int o = 4; o > 0; o >>= 1) v += __shfl_xor_sync(0xffu, v, o);
        if (t == 0) red[0] = v;
    }
    __syncthreads();
    float inv = 1.f / red[0];
    for (int i = t; i < N; i += 256) x[i] *= inv;
}

// ------------------------------------------------------------------
// fused dual softmax+combine (512 blocks):
//   blocks [0,256):  comb[r, D:]  = x2[r,:]        * (softmax(f1[r,:]) + 1)
//   blocks [256,512): comb[r, :D] = relu(x1[r,:])  * (softmax(f2[r,:]) + 1)
// ------------------------------------------------------------------
__global__ void softmax_combine2_kernel(const float* __restrict__ x2) {
    int rb = blockIdx.x;
    float* x;
    const float* bs;
    float* cb;
    int N, relu_base;
    if (rb < B_) {
        int r = rb;
        x = g_f1 + (size_t)r * E_;
        bs = x2 + (size_t)r * E_;
        cb = g_comb + (size_t)r * C_ + D_;
        N = E_; relu_base = 0;
    } else {
        int r = rb - B_;
        x = g_f2 + (size_t)r * D_;
        bs = g_x1 + (size_t)r * D_;
        cb = g_comb + (size_t)r * C_;
        N = D_; relu_base = 1;
    }
    int t = threadIdx.x;
    __shared__ float red[8];

    float m = -1e30f;
    for (int i = t; i < N; i += 256) m = fmaxf(m, x[i]);
#pragma unroll
    for (int o = 16; o > 0; o >>= 1) m = fmaxf(m, __shfl_xor_sync(0xffffffffu, m, o));
    if ((t & 31) == 0) red[t >> 5] = m;
    __syncthreads();
    if (t < 8) {
        float v = red[t];
#pragma unroll
        for (int o = 4; o > 0; o >>= 1) v = fmaxf(v, __shfl_xor_sync(0xffu, v, o));
        if (t == 0) red[0] = v;
    }
    __syncthreads();
    m = red[0];
    __syncthreads();

    float s = 0.f;
    for (int i = t; i < N; i += 256) {
        float e = __expf(x[i] - m);
        x[i] = e;
        s += e;
    }
#pragma unroll
    for (int o = 16; o > 0; o >>= 1) s += __shfl_xor_sync(0xffffffffu, s, o);
    if ((t & 31) == 0) red[t >> 5] = s;
    __syncthreads();
    if (t < 8) {
        float v = red[t];
#pragma unroll
        for (int o = 4; o > 0; o >>= 1) v += __shfl_xor_sync(0xffu, v, o);
        if (t == 0) red[0] = v;
    }
    __syncthreads();
    float inv = 1.f / red[0];
    for (int i = t; i < N; i += 256) {
        float b = bs[i];
        if (relu_base) b = fmaxf(b, 0.f);
        cb[i] = b * (x[i] * inv + 1.f);
    }
}

// ------------------------------------------------------------------
// out[b] = sum_h relu(g_h[b,h] + b_fc1[h]) * W2[h] + b2[0]
// ------------------------------------------------------------------
__global__ void final_kernel(const float* __restrict__ b1,
                             const float* __restrict__ W2,
                             const float* __restrict__ b2,
                             float* __restrict__ out) {
    int b = blockIdx.x;
    int t = threadIdx.x;
    __shared__ float red[8];
    float v = fmaxf(g_h[b * H_ + t] + b1[t], 0.f) * W2[t];
#pragma unroll
    for (int o = 16; o > 0; o >>= 1) v += __shfl_xor_sync(0xffffffffu, v, o);
    if ((t & 31) == 0) red[t >> 5] = v;
    __syncthreads();
    if (t < 8) {
        float s = red[t];
#pragma unroll
        for (int o = 4; o > 0; o >>= 1) s += __shfl_xor_sync(0xffu, s, o);
        if (t == 0) out[b] = s + b2[0];
    }
}

// ------------------------------------------------------------------
static inline int ceil_div(int a, int b) { return (a + b - 1) / b; }

extern "C" void kernel_launch(void* const* d_in, const int* in_sizes, int n_in,
                              void* d_out, int out_size) {
    const float* token_reps = (const float*)d_in[0];
    const int*   batch_lens = (const int*)d_in[1];
    const float* mol_repr   = (const float*)d_in[2];
    const float* W_prot     = (const float*)d_in[3];
    const float* b_prot     = (const float*)d_in[4];
    const float* W_attn     = (const float*)d_in[5];
    const float* b_attn     = (const float*)d_in[6];
    const float* W_fc1      = (const float*)d_in[7];
    const float* b_fc1      = (const float*)d_in[8];
    const float* W_fc2      = (const float*)d_in[9];
    const float* b_fc2      = (const float*)d_in[10];
    float* out = (float*)d_out;

    float *p_pooled, *p_x1, *p_q, *p_attn, *p_comb, *p_h;
    cudaGetSymbolAddress((void**)&p_pooled, g_pooled);
    cudaGetSymbolAddress((void**)&p_x1,     g_x1);
    cudaGetSymbolAddress((void**)&p_q,      g_q);
    cudaGetSymbolAddress((void**)&p_attn,   g_attn);
    cudaGetSymbolAddress((void**)&p_comb,   g_comb);
    cudaGetSymbolAddress((void**)&p_h,      g_h);

    // 1) init accumulators (biases folded in)
    init_all_kernel<<<ceil_div(B_ * D_, 256), 256>>>(b_prot, b_attn);

    // 2) ragged masked mean pool (direct write, scaled)
    pool_kernel<<<dim3(B_, D_ / 128), 128>>>(token_reps, batch_lens);

    // 3) x1(pre-relu) = pooled @ W_prot (+bias via init)  [256,1280], K=1280
    {
        int tps = 16;  // 80 tiles -> 5 splits
        dim3 grid(D_ / 64, B_ / 64, 5);   // 400 blocks
        gemm_kernel<0, 0, 0, 0><<<grid, 256>>>(
            p_pooled, W_prot, p_x1, B_, D_, D_, D_, D_, tps);
    }

    // 4) q = relu(x1) @ W_attn (+bias via init)  [256,300], K=1280
    {
        int tps = 8;   // 80 tiles -> 10 splits
        dim3 grid(ceil_div(E_, 64), B_ / 64, 10);  // 200 blocks
        gemm_kernel<0, 0, 1, 0><<<grid, 256>>>(
            p_x1, W_attn, p_q, B_, E_, D_, D_, E_, tps);
    }

    // 5) attn = softmax(q @ x2^T)  [256,256], K=300
    {
        int tps = 2;   // 19 tiles -> 10 splits
        dim3 grid(B_ / 64, B_ / 64, 10);  // 160 blocks
        gemm_kernel<0, 1, 0, 0><<<grid, 256>>>(
            p_q, mol_repr, p_attn, B_, B_, E_, E_, E_, tps);
        row_softmax_kernel<<<B_, 256>>>(p_attn, B_);
    }

    // 6+7) f1 = attn @ x2 ; f2 = attn^T @ relu(x1)  (one launch, z-split)
    {
        int z1 = 8, tps1 = 2;   // f1: 16 tiles -> 8 splits
        int z2 = 4, tps2 = 4;   // f2: 16 tiles -> 4 splits
        dim3 grid(D_ / 64, B_ / 64, z1 + z2);  // 20x4x12
        gemm67_kernel<<<grid, 256>>>(p_attn, mol_repr, z1, tps1, tps2);
    }

    // softmax+combine both halves (one launch, 512 blocks)
    softmax_combine2_kernel<<<2 * B_, 256>>>(mol_repr);

    // 8) h = combined @ W_fc1  [256,256], K=1580 (bias+relu folded into final)
    {
        int tps = 5;   // 99 tiles -> 20 splits
        dim3 grid(H_ / 64, B_ / 64, 20);  // 320 blocks
        gemm_kernel<0, 0, 0, 0><<<grid, 256>>>(
            p_comb, W_fc1, p_h, B_, H_, C_, C_, H_, tps);
    }

    // 9) out = relu(h + b_fc1) @ W_fc2 + b_fc2  [256,1]
    final_kernel<<<B_, 256>>>(b_fc1, W_fc2, b_fc2, out);
}

// round 9
// speedup vs baseline: 1.1708x; 1.1708x over previous
#include <cuda_runtime.h>
#include <cuda_bf16.h>
#include <mma.h>

using namespace nvcuda;

#define B_ 256
#define L_ 1026
#define D_ 1280
#define E_ 300
#define H_ 256
#define C_ 1580   // D_+E_

// SMEM layouts for the wmma GEMM
#define A_LD 20   // As[64][20]  (m-major, padded)
#define B_LD 68   // Bs[16][68]  (k-major, padded)

// ---- scratch (device globals; no allocation allowed) ----
__device__ float g_pooled[B_ * D_];
__device__ float g_inv[B_];
__device__ float g_x1[B_ * D_];      // PRE-relu x1 (consumers apply relu)
__device__ float g_q[B_ * E_];
__device__ float g_attn[B_ * B_];
__device__ float g_f1[B_ * E_];
__device__ float g_f2[B_ * D_];
__device__ float g_comb[B_ * C_];
__device__ float g_h[B_ * H_];

// ------------------------------------------------------------------
// init accumulators: pooled/f1/f2/attn/h <- 0; x1 <- b_prot; q <- b_attn
// plus inv[b] = 1/max(len-2,1)
// ------------------------------------------------------------------
__global__ void init_all_kernel(const int* __restrict__ lens,
                                const float* __restrict__ b_prot,
                                const float* __restrict__ b_attn) {
    int i = blockIdx.x * blockDim.x + threadIdx.x;
    if (i < B_ * D_) {
        g_pooled[i] = 0.f;
        g_f2[i] = 0.f;
        g_x1[i] = b_prot[i % D_];
    }
    if (i < B_ * E_) {
        g_f1[i] = 0.f;
        g_q[i] = b_attn[i % E_];
    }
    if (i < B_ * B_) g_attn[i] = 0.f;
    if (i < B_ * H_) g_h[i] = 0.f;
    if (i < B_) {
        int len = lens[i];
        g_inv[i] = 1.f / fmaxf((float)(len - 2), 1.f);
    }
}

// ------------------------------------------------------------------
// ragged masked sum pooling (CHUNKED, load-balanced):
// grid (B, ceil(L/TL)), block 320 (= D/4); each block sums its
// 128-row L-chunk ∩ [1, len-1) and atomicAdds its partial.
// ------------------------------------------------------------------
#define TL 128
__global__ void pool_kernel(const float* __restrict__ tok,
                            const int* __restrict__ lens) {
    int b = blockIdx.x;
    int len = lens[b];
    int l0 = blockIdx.y * TL;
    if (l0 < 1) l0 = 1;
    int l1 = min((int)(blockIdx.y + 1) * TL, len - 1);
    if (l0 >= l1) return;

    int d4 = threadIdx.x;  // 0..319
    const float4* base = reinterpret_cast<const float4*>(tok)
                       + (size_t)b * L_ * (D_ / 4) + d4;
    float4 acc = make_float4(0.f, 0.f, 0.f, 0.f);
    for (int l = l0; l < l1; l++) {
        float4 v = base[(size_t)l * (D_ / 4)];
        acc.x += v.x; acc.y += v.y; acc.z += v.z; acc.w += v.w;
    }
    float* o = g_pooled + b * D_ + d4 * 4;
    atomicAdd(o + 0, acc.x);
    atomicAdd(o + 1, acc.y);
    atomicAdd(o + 2, acc.z);
    atomicAdd(o + 3, acc.w);
}

// ------------------------------------------------------------------
// split-K tf32 wmma GEMM body.
//   C[M,N] += sum_{k in split} sc[m] * A_eff(m,k)*B_eff(k,n)
//   A_eff(m,k) = TA ? A[k*lda+m] : A[m*lda+k]   (relu'd if RELUA)
//   B_eff(k,n) = TB ? B[n*ldb+k] : B[k*ldb+n]   (relu'd if RELUB)
//   sc[m] = SCALEA ? rscale[m] : 1
// BM=BN=64, BK=16, 256 threads (8 warps, 2x4). C pre-initialized.
// ------------------------------------------------------------------
template <int TA, int TB, int RELUA, int RELUB, int SCALEA>
__device__ __forceinline__ void gemm_body(float* smem,
                                          const float* __restrict__ A,
                                          const float* __restrict__ B,
                                          const float* __restrict__ rscale,
                                          float* __restrict__ C,
                                          int M, int N, int K, int lda, int ldb,
                                          int tiles_per_split, int zi) {
    float* As = smem;              // [64][A_LD]
    float* Bs = smem + 1280;       // [16][B_LD]

    int k_begin = zi * tiles_per_split * 16;
    if (k_begin >= K) return;
    int k_end = min(k_begin + tiles_per_split * 16, K);

    int t = threadIdx.x;
    int bm = blockIdx.y * 64;
    int bn = blockIdx.x * 64;
    int wid = t >> 5;
    int warp_m = wid & 1;
    int warp_n = wid >> 1;

    wmma::fragment<wmma::accumulator, 16, 16, 8, float> cf[2];
    wmma::fill_fragment(cf[0], 0.f);
    wmma::fill_fragment(cf[1], 0.f);

    for (int k0 = k_begin; k0 < k_end; k0 += 16) {
        // ---- stage A tile -> As[m][k] ----
        if (!TA) {
            int mm = t >> 2;
            int kk4 = (t & 3) * 4;
            float4 v = make_float4(0.f, 0.f, 0.f, 0.f);
            if (k0 + kk4 < K)
                v = *reinterpret_cast<const float4*>(
                        &A[(size_t)(bm + mm) * lda + k0 + kk4]);
            if (RELUA) {
                v.x = fmaxf(v.x, 0.f); v.y = fmaxf(v.y, 0.f);
                v.z = fmaxf(v.z, 0.f); v.w = fmaxf(v.w, 0.f);
            }
            *reinterpret_cast<float4*>(&As[mm * A_LD + kk4]) = v;
        } else {
            int kk = t >> 4;
            int mm4 = (t & 15) * 4;
            float4 v = make_float4(0.f, 0.f, 0.f, 0.f);
            if (k0 + kk < K)
                v = *reinterpret_cast<const float4*>(
                        &A[(size_t)(k0 + kk) * lda + bm + mm4]);
            if (RELUA) {
                v.x = fmaxf(v.x, 0.f); v.y = fmaxf(v.y, 0.f);
                v.z = fmaxf(v.z, 0.f); v.w = fmaxf(v.w, 0.f);
            }
            As[(mm4 + 0) * A_LD + kk] = v.x;
            As[(mm4 + 1) * A_LD + kk] = v.y;
            As[(mm4 + 2) * A_LD + kk] = v.z;
            As[(mm4 + 3) * A_LD + kk] = v.w;
        }
        // ---- stage B tile -> Bs[k][n] ----
        if (!TB) {
            int kk = t >> 4;
            int nn4 = (t & 15) * 4;
            float4 v = make_float4(0.f, 0.f, 0.f, 0.f);
            if (k0 + kk < K && bn + nn4 < N)
                v = *reinterpret_cast<const float4*>(
                        &B[(size_t)(k0 + kk) * ldb + bn + nn4]);
            if (RELUB) {
                v.x = fmaxf(v.x, 0.f); v.y = fmaxf(v.y, 0.f);
                v.z = fmaxf(v.z, 0.f); v.w = fmaxf(v.w, 0.f);
            }
            *reinterpret_cast<float4*>(&Bs[kk * B_LD + nn4]) = v;
        } else {
            int nn = t >> 2;
            int kk4 = (t & 3) * 4;
            float4 v = make_float4(0.f, 0.f, 0.f, 0.f);
            if (bn + nn < N && k0 + kk4 < K)
                v = *reinterpret_cast<const float4*>(
                        &B[(size_t)(bn + nn) * ldb + k0 + kk4]);
            if (RELUB) {
                v.x = fmaxf(v.x, 0.f); v.y = fmaxf(v.y, 0.f);
                v.z = fmaxf(v.z, 0.f); v.w = fmaxf(v.w, 0.f);
            }
            Bs[(kk4 + 0) * B_LD + nn] = v.x;
            Bs[(kk4 + 1) * B_LD + nn] = v.y;
            Bs[(kk4 + 2) * B_LD + nn] = v.z;
            Bs[(kk4 + 3) * B_LD + nn] = v.w;
        }
        __syncthreads();

#pragma unroll
        for (int kk = 0; kk < 16; kk += 8) {
            wmma::fragment<wmma::matrix_b, 16, 16, 8,
                           wmma::precision::tf32, wmma::row_major> bf;
            wmma::load_matrix_sync(bf, &Bs[kk * B_LD + warp_n * 16], B_LD);
#pragma unroll
            for (int i = 0; i < bf.num_elements; i++)
                bf.x[i] = wmma::__float_to_tf32(bf.x[i]);
#pragma unroll
            for (int ma = 0; ma < 2; ma++) {
                wmma::fragment<wmma::matrix_a, 16, 16, 8,
                               wmma::precision::tf32, wmma::row_major> af;
                wmma::load_matrix_sync(
                    af, &As[(warp_m * 32 + ma * 16) * A_LD + kk], A_LD);
#pragma unroll
                for (int i = 0; i < af.num_elements; i++)
                    af.x[i] = wmma::__float_to_tf32(af.x[i]);
                wmma::mma_sync(cf[ma], af, bf, cf[ma]);
            }
        }
        __syncthreads();
    }

    // ---- epilogue: stage fragments to SMEM, then atomicAdd to C ----
    float* epi = smem + wid * 512;
    wmma::store_matrix_sync(epi, cf[0], 16, wmma::mem_row_major);
    wmma::store_matrix_sync(epi + 256, cf[1], 16, wmma::mem_row_major);
    __syncwarp();

    int lane = t & 31;
    for (int idx = lane; idx < 512; idx += 32) {
        int ma = idx >> 8;
        int r = (idx & 255) >> 4;
        int c = idx & 15;
        int gm = bm + warp_m * 32 + ma * 16 + r;
        int gn = bn + warp_n * 16 + c;
        if (gn < N) {
            float v = epi[ma * 256 + r * 16 + c];
            if (SCALEA) v *= rscale[gm];
            atomicAdd(&C[(size_t)gm * N + gn], v);
        }
    }
}

template <int TA, int TB, int RELUA, int RELUB, int SCALEA>
__global__ void gemm_kernel(const float* __restrict__ A,
                            const float* __restrict__ B,
                            const float* __restrict__ rscale,
                            float* __restrict__ C,
                            int M, int N, int K, int lda, int ldb,
                            int tiles_per_split) {
    __shared__ float smem[4096];
    gemm_body<TA, TB, RELUA, RELUB, SCALEA>(smem, A, B, rscale, C,
                                            M, N, K, lda, ldb,
                                            tiles_per_split, blockIdx.z);
}

// ------------------------------------------------------------------
// fused steps 6+7: blockIdx.z < z1 -> f1 = attn @ x2 ;
//                  else            -> f2 = attn^T @ relu(x1)
// grid (20, 4, z1+z2); f1 blocks with blockIdx.x >= 5 exit.
// ------------------------------------------------------------------
__global__ void gemm67_kernel(const float* __restrict__ attn,
                              const float* __restrict__ x2,
                              int z1, int tps1, int tps2) {
    __shared__ float smem[4096];
    if ((int)blockIdx.z < z1) {
        if (blockIdx.x >= (E_ + 63) / 64) return;
        gemm_body<0, 0, 0, 0, 0>(smem, attn, x2, nullptr, g_f1,
                                 B_, E_, B_, B_, E_, tps1, blockIdx.z);
    } else {
        gemm_body<1, 0, 0, 1, 0>(smem, attn, g_x1, nullptr, g_f2,
                                 B_, D_, B_, B_, D_, tps2, blockIdx.z - z1);
    }
}

// ------------------------------------------------------------------
// row softmax in-place: one block (256 threads) per row
// ------------------------------------------------------------------
__global__ void row_softmax_kernel(float* __restrict__ X, int N) {
    int r = blockIdx.x;
    float* x = X + (size_t)r * N;
    int t = threadIdx.x;
    __shared__ float red[8];

    float m = -1e30f;
    for (int i = t; i < N; i += 256) m = fmaxf(m, x[i]);
#pragma unroll
    for (int o = 16; o > 0; o >>= 1) m = fmaxf(m, __shfl_xor_sync(0xffffffffu, m, o));
    if ((t & 31) == 0) red[t >> 5] = m;
    __syncthreads();
    if (t < 8) {
        float v = red[t];
#pragma unroll
        for (int o = 4; o > 0; o >>= 1) v = fmaxf(v, __shfl_xor_sync(0xffu, v, o));
        if (t == 0) red[0] = v;
    }
    __syncthreads();
    m = red[0];
    __syncthreads();

    float s = 0.f;
    for (int i = t; i < N; i += 256) {
        float e = __expf(x[i] - m);
        x[i] = e;
        s += e;
    }
#pragma unroll
    for (int o = 16; o > 0; o >>= 1) s += __shfl_xor_sync(0xffffffffu, s, o);
    if ((t & 31) == 0) red[t >> 5] = s;
    __syncthreads();
    if (t < 8) {
        float v = red[t];
#pragma unroll
        for (int o = 4; o > 0; o >>= 1) v += __shfl_xor_sync(0xffu, v, o);
        if (t == 0) red[0] = v;
    }
    __syncthreads();
    float inv = 1.f / red[0];
    for (int i = t; i < N; i += 256) x[i] *= inv;
}

// ------------------------------------------------------------------
// fused dual softmax+combine (512 blocks):
//   blocks [0,256):  comb[r, D:]  = x2[r,:]       * (softmax(f1[r,:]) + 1)
//   blocks [256,512): comb[r, :D] = relu(x1[r,:]) * (softmax(f2[r,:]) + 1)
// ------------------------------------------------------------------
__global__ void softmax_combine2_kernel(const float* __restrict__ x2) {
    int rb = blockIdx.x;
    float* x;
    const float* bs;
    float* cb;
    int N, relu_base;
    if (rb < B_) {
        int r = rb;
        x = g_f1 + (size_t)r * E_;
        bs = x2 + (size_t)r * E_;
        cb = g_comb + (size_t)r * C_ + D_;
        N = E_; relu_base = 0;
    } else {
        int r = rb - B_;
        x = g_f2 + (size_t)r * D_;
        bs = g_x1 + (size_t)r * D_;
        cb = g_comb + (size_t)r * C_;
        N = D_; relu_base = 1;
    }
    int t = threadIdx.x;
    __shared__ float red[8];

    float m = -1e30f;
    for (int i = t; i < N; i += 256) m = fmaxf(m, x[i]);
#pragma unroll
    for (int o = 16; o > 0; o >>= 1) m = fmaxf(m, __shfl_xor_sync(0xffffffffu, m, o));
    if ((t & 31) == 0) red[t >> 5] = m;
    __syncthreads();
    if (t < 8) {
        float v = red[t];
#pragma unroll
        for (int o = 4; o > 0; o >>= 1) v = fmaxf(v, __shfl_xor_sync(0xffu, v, o));
        if (t == 0) red[0] = v;
    }
    __syncthreads();
    m = red[0];
    __syncthreads();

    float s = 0.f;
    for (int i = t; i < N; i += 256) {
        float e = __expf(x[i] - m);
        x[i] = e;
        s += e;
    }
#pragma unroll
    for (int o = 16; o > 0; o >>= 1) s += __shfl_xor_sync(0xffffffffu, s, o);
    if ((t & 31) == 0) red[t >> 5] = s;
    __syncthreads();
    if (t < 8) {
        float v = red[t];
#pragma unroll
        for (int o = 4; o > 0; o >>= 1) v += __shfl_xor_sync(0xffu, v, o);
        if (t == 0) red[0] = v;
    }
    __syncthreads();
    float inv = 1.f / red[0];
    for (int i = t; i < N; i += 256) {
        float b = bs[i];
        if (relu_base) b = fmaxf(b, 0.f);
        cb[i] = b * (x[i] * inv + 1.f);
    }
}

// ------------------------------------------------------------------
// out[b] = sum_h relu(g_h[b,h] + b_fc1[h]) * W2[h] + b2[0]
// ------------------------------------------------------------------
__global__ void final_kernel(const float* __restrict__ b1,
                             const float* __restrict__ W2,
                             const float* __restrict__ b2,
                             float* __restrict__ out) {
    int b = blockIdx.x;
    int t = threadIdx.x;
    __shared__ float red[8];
    float v = fmaxf(g_h[b * H_ + t] + b1[t], 0.f) * W2[t];
#pragma unroll
    for (int o = 16; o > 0; o >>= 1) v += __shfl_xor_sync(0xffffffffu, v, o);
    if ((t & 31) == 0) red[t >> 5] = v;
    __syncthreads();
    if (t < 8) {
        float s = red[t];
#pragma unroll
        for (int o = 4; o > 0; o >>= 1) s += __shfl_xor_sync(0xffu, s, o);
        if (t == 0) out[b] = s + b2[0];
    }
}

// ------------------------------------------------------------------
static inline int ceil_div(int a, int b) { return (a + b - 1) / b; }

extern "C" void kernel_launch(void* const* d_in, const int* in_sizes, int n_in,
                              void* d_out, int out_size) {
    const float* token_reps = (const float*)d_in[0];
    const int*   batch_lens = (const int*)d_in[1];
    const float* mol_repr   = (const float*)d_in[2];
    const float* W_prot     = (const float*)d_in[3];
    const float* b_prot     = (const float*)d_in[4];
    const float* W_attn     = (const float*)d_in[5];
    const float* b_attn     = (const float*)d_in[6];
    const float* W_fc1      = (const float*)d_in[7];
    const float* b_fc1      = (const float*)d_in[8];
    const float* W_fc2      = (const float*)d_in[9];
    const float* b_fc2      = (const float*)d_in[10];
    float* out = (float*)d_out;

    float *p_pooled, *p_inv, *p_x1, *p_q, *p_attn, *p_comb, *p_h;
    cudaGetSymbolAddress((void**)&p_pooled, g_pooled);
    cudaGetSymbolAddress((void**)&p_inv,    g_inv);
    cudaGetSymbolAddress((void**)&p_x1,     g_x1);
    cudaGetSymbolAddress((void**)&p_q,      g_q);
    cudaGetSymbolAddress((void**)&p_attn,   g_attn);
    cudaGetSymbolAddress((void**)&p_comb,   g_comb);
    cudaGetSymbolAddress((void**)&p_h,      g_h);

    // 1) init accumulators (biases folded in) + inverse counts
    init_all_kernel<<<ceil_div(B_ * D_, 256), 256>>>(batch_lens, b_prot, b_attn);

    // 2) ragged masked sum pool (chunked, load-balanced)
    pool_kernel<<<dim3(B_, ceil_div(L_, TL)), D_ / 4>>>(token_reps, batch_lens);

    // 3) x1(pre-relu) = (pooled*inv) @ W_prot (+bias via init)  [256,1280], K=1280
    {
        int tps = 16;  // 80 tiles -> 5 splits
        dim3 grid(D_ / 64, B_ / 64, 5);   // 400 blocks
        gemm_kernel<0, 0, 0, 0, 1><<<grid, 256>>>(
            p_pooled, W_prot, p_inv, p_x1, B_, D_, D_, D_, D_, tps);
    }

    // 4) q = relu(x1) @ W_attn (+bias via init)  [256,300], K=1280
    {
        int tps = 8;   // 80 tiles -> 10 splits
        dim3 grid(ceil_div(E_, 64), B_ / 64, 10);  // 200 blocks
        gemm_kernel<0, 0, 1, 0, 0><<<grid, 256>>>(
            p_x1, W_attn, nullptr, p_q, B_, E_, D_, D_, E_, tps);
    }

    // 5) attn = softmax(q @ x2^T)  [256,256], K=300
    {
        int tps = 2;   // 19 tiles -> 10 splits
        dim3 grid(B_ / 64, B_ / 64, 10);  // 160 blocks
        gemm_kernel<0, 1, 0, 0, 0><<<grid, 256>>>(
            p_q, mol_repr, nullptr, p_attn, B_, B_, E_, E_, E_, tps);
        row_softmax_kernel<<<B_, 256>>>(p_attn, B_);
    }

    // 6+7) f1 = attn @ x2 ; f2 = attn^T @ relu(x1)  (one launch, z-split)
    {
        int z1 = 8, tps1 = 2;   // f1: 16 tiles -> 8 splits
        int z2 = 4, tps2 = 4;   // f2: 16 tiles -> 4 splits
        dim3 grid(D_ / 64, B_ / 64, z1 + z2);  // 20x4x12
        gemm67_kernel<<<grid, 256>>>(p_attn, mol_repr, z1, tps1, tps2);
    }

    // softmax+combine both halves (one launch, 512 blocks)
    softmax_combine2_kernel<<<2 * B_, 256>>>(mol_repr);

    // 8) h = combined @ W_fc1  [256,256], K=1580 (bias+relu folded into final)
    {
        int tps = 5;   // 99 tiles -> 20 splits
        dim3 grid(H_ / 64, B_ / 64, 20);  // 320 blocks
        gemm_kernel<0, 0, 0, 0, 0><<<grid, 256>>>(
            p_comb, W_fc1, nullptr, p_h, B_, H_, C_, C_, H_, tps);
    }

    // 9) out = relu(h + b_fc1) @ W_fc2 + b_fc2  [256,1]
    final_kernel<<<B_, 256>>>(b_fc1, W_fc2, b_fc2, out);
}

// round 12
// speedup vs baseline: 1.2204x; 1.0424x over previous
#include <cuda_runtime.h>
#include <cuda_bf16.h>
#include <mma.h>

using namespace nvcuda;

#define B_ 256
#define L_ 1026
#define D_ 1280
#define E_ 300
#define H_ 256
#define C_ 1580   // D_+E_

// SMEM layouts for the wmma GEMM (BK=32)
#define A_LD 36   // As[64][36]  (m-major, padded)
#define B_LD 68   // Bs[32][68]  (k-major, padded)
// As: 64*36 = 2304 floats; Bs: 32*68 = 2176; total 4480 (epi needs 4096)

// ---- scratch (device globals; no allocation allowed) ----
__device__ float g_pooled[B_ * D_];
__device__ float g_inv[B_];
__device__ float g_x1[B_ * D_];      // PRE-relu x1 (consumers apply relu)
__device__ float g_q[B_ * E_];
__device__ float g_attn[B_ * B_];
__device__ float g_f1[B_ * E_];
__device__ float g_f2[B_ * D_];
__device__ float g_comb[B_ * C_];
__device__ float g_h[B_ * H_];

// ------------------------------------------------------------------
// init accumulators + inv counts
// ------------------------------------------------------------------
__global__ void init_all_kernel(const int* __restrict__ lens,
                                const float* __restrict__ b_prot,
                                const float* __restrict__ b_attn) {
    int i = blockIdx.x * blockDim.x + threadIdx.x;
    if (i < B_ * D_) {
        g_pooled[i] = 0.f;
        g_f2[i] = 0.f;
        g_x1[i] = b_prot[i % D_];
    }
    if (i < B_ * E_) {
        g_f1[i] = 0.f;
        g_q[i] = b_attn[i % E_];
    }
    if (i < B_ * B_) g_attn[i] = 0.f;
    if (i < B_ * H_) g_h[i] = 0.f;
    if (i < B_) {
        int len = lens[i];
        g_inv[i] = 1.f / fmaxf((float)(len - 2), 1.f);
    }
}

// ------------------------------------------------------------------
// ragged masked sum pooling (chunked, load-balanced)
// ------------------------------------------------------------------
#define TL 128
__global__ void pool_kernel(const float* __restrict__ tok,
                            const int* __restrict__ lens) {
    int b = blockIdx.x;
    int len = lens[b];
    int l0 = blockIdx.y * TL;
    if (l0 < 1) l0 = 1;
    int l1 = min((int)(blockIdx.y + 1) * TL, len - 1);
    if (l0 >= l1) return;

    int d4 = threadIdx.x;  // 0..319
    const float4* base = reinterpret_cast<const float4*>(tok)
                       + (size_t)b * L_ * (D_ / 4) + d4;
    float4 acc = make_float4(0.f, 0.f, 0.f, 0.f);
    for (int l = l0; l < l1; l++) {
        float4 v = base[(size_t)l * (D_ / 4)];
        acc.x += v.x; acc.y += v.y; acc.z += v.z; acc.w += v.w;
    }
    float* o = g_pooled + b * D_ + d4 * 4;
    atomicAdd(o + 0, acc.x);
    atomicAdd(o + 1, acc.y);
    atomicAdd(o + 2, acc.z);
    atomicAdd(o + 3, acc.w);
}

// ------------------------------------------------------------------
// relu + tf32-truncate a float4 (conversion hoisted into staging)
// ------------------------------------------------------------------
template <int RELU>
__device__ __forceinline__ float4 prep4(float4 v) {
    if (RELU) {
        v.x = fmaxf(v.x, 0.f); v.y = fmaxf(v.y, 0.f);
        v.z = fmaxf(v.z, 0.f); v.w = fmaxf(v.w, 0.f);
    }
    v.x = wmma::__float_to_tf32(v.x);
    v.y = wmma::__float_to_tf32(v.y);
    v.z = wmma::__float_to_tf32(v.z);
    v.w = wmma::__float_to_tf32(v.w);
    return v;
}

// ------------------------------------------------------------------
// split-K tf32 wmma GEMM body, BK=32.
//   C[M,N] += sum_{k in split} sc[m] * A_eff(m,k)*B_eff(k,n)
// BM=BN=64, BK=32, 256 threads (8 warps, 2x4). C pre-initialized.
// tf32 conversion applied at staging time; inner loop pure MMA.
// ------------------------------------------------------------------
template <int TA, int TB, int RELUA, int RELUB, int SCALEA>
__device__ __forceinline__ void gemm_body(float* smem,
                                          const float* __restrict__ A,
                                          const float* __restrict__ B,
                                          const float* __restrict__ rscale,
                                          float* __restrict__ C,
                                          int M, int N, int K, int lda, int ldb,
                                          int tiles_per_split, int zi) {
    float* As = smem;              // [64][A_LD]
    float* Bs = smem + 2304;       // [32][B_LD]

    int k_begin = zi * tiles_per_split * 32;
    if (k_begin >= K) return;
    int k_end = min(k_begin + tiles_per_split * 32, K);

    int t = threadIdx.x;
    int bm = blockIdx.y * 64;
    int bn = blockIdx.x * 64;
    int wid = t >> 5;
    int warp_m = wid & 1;
    int warp_n = wid >> 1;

    wmma::fragment<wmma::accumulator, 16, 16, 8, float> cf[2];
    wmma::fill_fragment(cf[0], 0.f);
    wmma::fill_fragment(cf[1], 0.f);

    for (int k0 = k_begin; k0 < k_end; k0 += 32) {
        // ---- stage A tile -> As[m][k], tf32-converted ----
        if (!TA) {
            int mm = t >> 2;            // 0..63
            int kk8 = (t & 3) * 8;      // 0,8,16,24
#pragma unroll
            for (int h = 0; h < 2; h++) {
                int kk4 = kk8 + h * 4;
                float4 v = make_float4(0.f, 0.f, 0.f, 0.f);
                if (k0 + kk4 < K)
                    v = *reinterpret_cast<const float4*>(
                            &A[(size_t)(bm + mm) * lda + k0 + kk4]);
                v = prep4<RELUA>(v);
                *reinterpret_cast<float4*>(&As[mm * A_LD + kk4]) = v;
            }
        } else {
            int kk = t >> 3;            // 0..31
            int mm8 = (t & 7) * 8;
#pragma unroll
            for (int h = 0; h < 2; h++) {
                int mm4 = mm8 + h * 4;
                float4 v = make_float4(0.f, 0.f, 0.f, 0.f);
                if (k0 + kk < K)
                    v = *reinterpret_cast<const float4*>(
                            &A[(size_t)(k0 + kk) * lda + bm + mm4]);
                v = prep4<RELUA>(v);
                As[(mm4 + 0) * A_LD + kk] = v.x;
                As[(mm4 + 1) * A_LD + kk] = v.y;
                As[(mm4 + 2) * A_LD + kk] = v.z;
                As[(mm4 + 3) * A_LD + kk] = v.w;
            }
        }
        // ---- stage B tile -> Bs[k][n], tf32-converted ----
        if (!TB) {
            int kk = t >> 3;            // 0..31
            int nn8 = (t & 7) * 8;
#pragma unroll
            for (int h = 0; h < 2; h++) {
                int nn4 = nn8 + h * 4;
                float4 v = make_float4(0.f, 0.f, 0.f, 0.f);
                if (k0 + kk < K && bn + nn4 < N)
                    v = *reinterpret_cast<const float4*>(
                            &B[(size_t)(k0 + kk) * ldb + bn + nn4]);
                v = prep4<RELUB>(v);
                *reinterpret_cast<float4*>(&Bs[kk * B_LD + nn4]) = v;
            }
        } else {
            int nn = t >> 2;            // 0..63
            int kk8 = (t & 3) * 8;
#pragma unroll
            for (int h = 0; h < 2; h++) {
                int kk4 = kk8 + h * 4;
                float4 v = make_float4(0.f, 0.f, 0.f, 0.f);
                if (bn + nn < N && k0 + kk4 < K)
                    v = *reinterpret_cast<const float4*>(
                            &B[(size_t)(bn + nn) * ldb + k0 + kk4]);
                v = prep4<RELUB>(v);
                Bs[(kk4 + 0) * B_LD + nn] = v.x;
                Bs[(kk4 + 1) * B_LD + nn] = v.y;
                Bs[(kk4 + 2) * B_LD + nn] = v.z;
                Bs[(kk4 + 3) * B_LD + nn] = v.w;
            }
        }
        __syncthreads();

#pragma unroll
        for (int kk = 0; kk < 32; kk += 8) {
            wmma::fragment<wmma::matrix_b, 16, 16, 8,
                           wmma::precision::tf32, wmma::row_major> bf;
            wmma::load_matrix_sync(bf, &Bs[kk * B_LD + warp_n * 16], B_LD);
#pragma unroll
            for (int ma = 0; ma < 2; ma++) {
                wmma::fragment<wmma::matrix_a, 16, 16, 8,
                               wmma::precision::tf32, wmma::row_major> af;
                wmma::load_matrix_sync(
                    af, &As[(warp_m * 32 + ma * 16) * A_LD + kk], A_LD);
                wmma::mma_sync(cf[ma], af, bf, cf[ma]);
            }
        }
        __syncthreads();
    }

    // ---- epilogue: stage fragments to SMEM, then atomicAdd to C ----
    float* epi = smem + wid * 512;
    wmma::store_matrix_sync(epi, cf[0], 16, wmma::mem_row_major);
    wmma::store_matrix_sync(epi + 256, cf[1], 16, wmma::mem_row_major);
    __syncwarp();

    int lane = t & 31;
    for (int idx = lane; idx < 512; idx += 32) {
        int ma = idx >> 8;
        int r = (idx & 255) >> 4;
        int c = idx & 15;
        int gm = bm + warp_m * 32 + ma * 16 + r;
        int gn = bn + warp_n * 16 + c;
        if (gn < N) {
            float v = epi[ma * 256 + r * 16 + c];
            if (SCALEA) v *= rscale[gm];
            atomicAdd(&C[(size_t)gm * N + gn], v);
        }
    }
}

template <int TA, int TB, int RELUA, int RELUB, int SCALEA>
__global__ void gemm_kernel(const float* __restrict__ A,
                            const float* __restrict__ B,
                            const float* __restrict__ rscale,
                            float* __restrict__ C,
                            int M, int N, int K, int lda, int ldb,
                            int tiles_per_split) {
    __shared__ float smem[4480];
    gemm_body<TA, TB, RELUA, RELUB, SCALEA>(smem, A, B, rscale, C,
                                            M, N, K, lda, ldb,
                                            tiles_per_split, blockIdx.z);
}

// ------------------------------------------------------------------
// fused steps 6+7: blockIdx.z < z1 -> f1 = attn @ x2 ;
//                  else            -> f2 = attn^T @ relu(x1)
// ------------------------------------------------------------------
__global__ void gemm67_kernel(const float* __restrict__ attn,
                              const float* __restrict__ x2,
                              int z1, int tps1, int tps2) {
    __shared__ float smem[4480];
    if ((int)blockIdx.z < z1) {
        if (blockIdx.x >= (E_ + 63) / 64) return;
        gemm_body<0, 0, 0, 0, 0>(smem, attn, x2, nullptr, g_f1,
                                 B_, E_, B_, B_, E_, tps1, blockIdx.z);
    } else {
        gemm_body<1, 0, 0, 1, 0>(smem, attn, g_x1, nullptr, g_f2,
                                 B_, D_, B_, B_, D_, tps2, blockIdx.z - z1);
    }
}

// ------------------------------------------------------------------
// row softmax in-place: one block (256 threads) per row
// ------------------------------------------------------------------
__global__ void row_softmax_kernel(float* __restrict__ X, int N) {
    int r = blockIdx.x;
    float* x = X + (size_t)r * N;
    int t = threadIdx.x;
    __shared__ float red[8];

    float m = -1e30f;
    for (int i = t; i < N; i += 256) m = fmaxf(m, x[i]);
#pragma unroll
    for (int o = 16; o > 0; o >>= 1) m = fmaxf(m, __shfl_xor_sync(0xffffffffu, m, o));
    if ((t & 31) == 0) red[t >> 5] = m;
    __syncthreads();
    if (t < 8) {
        float v = red[t];
#pragma unroll
        for (int o = 4; o > 0; o >>= 1) v = fmaxf(v, __shfl_xor_sync(0xffu, v, o));
        if (t == 0) red[0] = v;
    }
    __syncthreads();
    m = red[0];
    __syncthreads();

    float s = 0.f;
    for (int i = t; i < N; i += 256) {
        float e = __expf(x[i] - m);
        x[i] = e;
        s += e;
    }
#pragma unroll
    for (int o = 16; o > 0; o >>= 1) s += __shfl_xor_sync(0xffffffffu, s, o);
    if ((t & 31) == 0) red[t >> 5] = s;
    __syncthreads();
    if (t < 8) {
        float v = red[t];
#pragma unroll
        for (int o = 4; o > 0; o >>= 1) v += __shfl_xor_sync(0xffu, v, o);
        if (t == 0) red[0] = v;
    }
    __syncthreads();
    float inv = 1.f / red[0];
    for (int i = t; i < N; i += 256) x[i] *= inv;
}

// ------------------------------------------------------------------
// fused dual softmax+combine (512 blocks)
// ------------------------------------------------------------------
__global__ void softmax_combine2_kernel(const float* __restrict__ x2) {
    int rb = blockIdx.x;
    float* x;
    const float* bs;
    float* cb;
    int N, relu_base;
    if (rb < B_) {
        int r = rb;
        x = g_f1 + (size_t)r * E_;
        bs = x2 + (size_t)r * E_;
        cb = g_comb + (size_t)r * C_ + D_;
        N = E_; relu_base = 0;
    } else {
        int r = rb - B_;
        x = g_f2 + (size_t)r * D_;
        bs = g_x1 + (size_t)r * D_;
        cb = g_comb + (size_t)r * C_;
        N = D_; relu_base = 1;
    }
    int t = threadIdx.x;
    __shared__ float red[8];

    float m = -1e30f;
    for (int i = t; i < N; i += 256) m = fmaxf(m, x[i]);
#pragma unroll
    for (int o = 16; o > 0; o >>= 1) m = fmaxf(m, __shfl_xor_sync(0xffffffffu, m, o));
    if ((t & 31) == 0) red[t >> 5] = m;
    __syncthreads();
    if (t < 8) {
        float v = red[t];
#pragma unroll
        for (int o = 4; o > 0; o >>= 1) v = fmaxf(v, __shfl_xor_sync(0xffu, v, o));
        if (t == 0) red[0] = v;
    }
    __syncthreads();
    m = red[0];
    __syncthreads();

    float s = 0.f;
    for (int i = t; i < N; i += 256) {
        float e = __expf(x[i] - m);
        x[i] = e;
        s += e;
    }
#pragma unroll
    for (int o = 16; o > 0; o >>= 1) s += __shfl_xor_sync(0xffffffffu, s, o);
    if ((t & 31) == 0) red[t >> 5] = s;
    __syncthreads();
    if (t < 8) {
        float v = red[t];
#pragma unroll
        for (int o = 4; o > 0; o >>= 1) v += __shfl_xor_sync(0xffu, v, o);
        if (t == 0) red[0] = v;
    }
    __syncthreads();
    float inv = 1.f / red[0];
    for (int i = t; i < N; i += 256) {
        float b = bs[i];
        if (relu_base) b = fmaxf(b, 0.f);
        cb[i] = b * (x[i] * inv + 1.f);
    }
}

// ------------------------------------------------------------------
// out[b] = sum_h relu(g_h[b,h] + b_fc1[h]) * W2[h] + b2[0]
// ------------------------------------------------------------------
__global__ void final_kernel(const float* __restrict__ b1,
                             const float* __restrict__ W2,
                             const float* __restrict__ b2,
                             float* __restrict__ out) {
    int b = blockIdx.x;
    int t = threadIdx.x;
    __shared__ float red[8];
    float v = fmaxf(g_h[b * H_ + t] + b1[t], 0.f) * W2[t];
#pragma unroll
    for (int o = 16; o > 0; o >>= 1) v += __shfl_xor_sync(0xffffffffu, v, o);
    if ((t & 31) == 0) red[t >> 5] = v;
    __syncthreads();
    if (t < 8) {
        float s = red[t];
#pragma unroll
        for (int o = 4; o > 0; o >>= 1) s += __shfl_xor_sync(0xffu, s, o);
        if (t == 0) out[b] = s + b2[0];
    }
}

// ------------------------------------------------------------------
static inline int ceil_div(int a, int b) { return (a + b - 1) / b; }

extern "C" void kernel_launch(void* const* d_in, const int* in_sizes, int n_in,
                              void* d_out, int out_size) {
    const float* token_reps = (const float*)d_in[0];
    const int*   batch_lens = (const int*)d_in[1];
    const float* mol_repr   = (const float*)d_in[2];
    const float* W_prot     = (const float*)d_in[3];
    const float* b_prot     = (const float*)d_in[4];
    const float* W_attn     = (const float*)d_in[5];
    const float* b_attn     = (const float*)d_in[6];
    const float* W_fc1      = (const float*)d_in[7];
    const float* b_fc1      = (const float*)d_in[8];
    const float* W_fc2      = (const float*)d_in[9];
    const float* b_fc2      = (const float*)d_in[10];
    float* out = (float*)d_out;

    float *p_pooled, *p_inv, *p_x1, *p_q, *p_attn, *p_comb, *p_h;
    cudaGetSymbolAddress((void**)&p_pooled, g_pooled);
    cudaGetSymbolAddress((void**)&p_inv,    g_inv);
    cudaGetSymbolAddress((void**)&p_x1,     g_x1);
    cudaGetSymbolAddress((void**)&p_q,      g_q);
    cudaGetSymbolAddress((void**)&p_attn,   g_attn);
    cudaGetSymbolAddress((void**)&p_comb,   g_comb);
    cudaGetSymbolAddress((void**)&p_h,      g_h);

    // 1) init accumulators (biases folded in) + inverse counts
    init_all_kernel<<<ceil_div(B_ * D_, 256), 256>>>(batch_lens, b_prot, b_attn);

    // 2) ragged masked sum pool (chunked, load-balanced)
    pool_kernel<<<dim3(B_, ceil_div(L_, TL)), D_ / 4>>>(token_reps, batch_lens);

    // 3) x1(pre-relu) = (pooled*inv) @ W_prot  [256,1280], K=1280 (40 k-tiles)
    {
        int tps = 8;   // -> 5 splits
        dim3 grid(D_ / 64, B_ / 64, 5);   // 400 blocks
        gemm_kernel<0, 0, 0, 0, 1><<<grid, 256>>>(
            p_pooled, W_prot, p_inv, p_x1, B_, D_, D_, D_, D_, tps);
    }

    // 4) q = relu(x1) @ W_attn  [256,300], K=1280 (40 k-tiles)
    {
        int tps = 4;   // -> 10 splits
        dim3 grid(ceil_div(E_, 64), B_ / 64, 10);  // 200 blocks
        gemm_kernel<0, 0, 1, 0, 0><<<grid, 256>>>(
            p_x1, W_attn, nullptr, p_q, B_, E_, D_, D_, E_, tps);
    }

    // 5) attn = softmax(q @ x2^T)  [256,256], K=300 (10 k-tiles)
    {
        int tps = 1;   // -> 10 splits
        dim3 grid(B_ / 64, B_ / 64, 10);  // 160 blocks
        gemm_kernel<0, 1, 0, 0, 0><<<grid, 256>>>(
            p_q, mol_repr, nullptr, p_attn, B_, B_, E_, E_, E_, tps);
        row_softmax_kernel<<<B_, 256>>>(p_attn, B_);
    }

    // 6+7) f1 = attn @ x2 ; f2 = attn^T @ relu(x1)  (one launch, z-split)
    {
        int z1 = 8, tps1 = 1;   // f1: K=256 -> 8 tiles -> 8 splits
        int z2 = 4, tps2 = 2;   // f2: 8 tiles -> 4 splits
        dim3 grid(D_ / 64, B_ / 64, z1 + z2);  // 20x4x12
        gemm67_kernel<<<grid, 256>>>(p_attn, mol_repr, z1, tps1, tps2);
    }

    // softmax+combine both halves (one launch, 512 blocks)
    softmax_combine2_kernel<<<2 * B_, 256>>>(mol_repr);

    // 8) h = combined @ W_fc1  [256,256], K=1580 (50 k-tiles)
    {
        int tps = 3;   // -> 17 splits
        dim3 grid(H_ / 64, B_ / 64, 17);  // 272 blocks
        gemm_kernel<0, 0, 0, 0, 0><<<grid, 256>>>(
            p_comb, W_fc1, nullptr, p_h, B_, H_, C_, C_, H_, tps);
    }

    // 9) out = relu(h + b_fc1) @ W_fc2 + b_fc2  [256,1]
    final_kernel<<<B_, 256>>>(b_fc1, W_fc2, b_fc2, out);
}